// round 1
// baseline (speedup 1.0000x reference)
#include <cuda_runtime.h>
#include <math.h>

#define B_    256
#define T_    128
#define WD_   300
#define DD_   50
#define IN_DIM_ 400
#define ATTN_ 700
#define NF_   512
#define NCLS_ 19
#define M_    (B_*T_)            // 32768
#define FEAT_ (NF_ + 2*IN_DIM_)  // 1312

// ---------------- scratch (static device memory; no allocations) ----------------
__device__ float g_inp[M_*IN_DIM_];          // [B,T,400] gathered embeddings (unmasked)
__device__ float g_Wt[3*IN_DIM_*NF_];        // conv weights transposed to [h][i][o]
__device__ float g_WaT[2][IN_DIM_*ATTN_];    // Wa[:, :400] transposed to [i][e]
__device__ float g_c[2][B_*ATTN_];           // arg-embedding contribution per (b,e)
__device__ float g_scores[2][B_*T_];
__device__ float g_a[2][B_*T_];
__device__ float g_cnnmax[B_*NF_];           // max over t of conv (pre-bias, pre-tanh)
__device__ float g_v[2][B_*IN_DIM_];

// ---------------- weight prep: transposes for coalesced GEMM B-loads ----------------
__global__ void k_prep(const float* __restrict__ conv_w,
                       const float* __restrict__ Wa1,
                       const float* __restrict__ Wa2) {
    int idx = blockIdx.x * blockDim.x + threadIdx.x;
    const int NWT = 3*IN_DIM_*NF_;      // 614400
    const int NWA = IN_DIM_*ATTN_;      // 280000
    if (idx < NWT) {
        int h = idx / (IN_DIM_*NF_);
        int rem = idx % (IN_DIM_*NF_);
        int i = rem / NF_, o = rem % NF_;
        g_Wt[idx] = conv_w[o*(IN_DIM_*3) + i*3 + h];
    } else if (idx < NWT + 2*NWA) {
        int j = idx - NWT;
        int w = j / NWA;
        int r = j % NWA;
        int i = r / ATTN_, e = r % ATTN_;
        const float* Wa = w ? Wa2 : Wa1;
        g_WaT[w][r] = Wa[e*ATTN_ + i];
    }
}

// ---------------- gather embeddings into inp[B,T,400] ----------------
__global__ void k_gather(const int* __restrict__ words,
                         const int* __restrict__ d1i,
                         const int* __restrict__ d2i,
                         const float* __restrict__ wemb,
                         const float* __restrict__ d1e,
                         const float* __restrict__ d2e) {
    int idx = blockIdx.x * blockDim.x + threadIdx.x;
    if (idx >= M_*IN_DIM_) return;
    int m = idx / IN_DIM_, d = idx % IN_DIM_;
    float v;
    if (d < WD_)            v = wemb[words[m]*WD_ + d];
    else if (d < WD_+DD_)   v = d1e[d1i[m]*DD_ + (d - WD_)];
    else                    v = d2e[d2i[m]*DD_ + (d - WD_ - DD_)];
    g_inp[idx] = v;
}

// ---------------- c[b,e] = arg_emb[b,:300] . Wa[e, 400:700] ----------------
__global__ void k_argc(const int* __restrict__ arg1,
                       const int* __restrict__ arg2,
                       const float* __restrict__ wemb,
                       const float* __restrict__ Wa1,
                       const float* __restrict__ Wa2) {
    int b = blockIdx.x, w = blockIdx.y;
    const int* arg = w ? arg2 : arg1;
    const float* Wa = w ? Wa2 : Wa1;
    __shared__ float ae[WD_];
    int aidx = arg[b];
    for (int d = threadIdx.x; d < WD_; d += blockDim.x)
        ae[d] = wemb[aidx*WD_ + d];
    __syncthreads();
    for (int e = threadIdx.x; e < ATTN_; e += blockDim.x) {
        const float* row = Wa + e*ATTN_ + IN_DIM_;
        float s = 0.f;
        #pragma unroll 4
        for (int d = 0; d < WD_; ++d) s += ae[d] * row[d];
        g_c[w][b*ATTN_ + e] = s;
    }
}

// ---------------- conv GEMM: 128x128 tile, K=1200, fused time-max ----------------
// out[b,nf,t] = sum_{i,h} inp[b,t+h-1,i]*mask[b,t+h-1] * Wt[h,i,nf]
// M-tile = one full batch (128 rows = T) -> max over rows fully in-tile.
__global__ __launch_bounds__(256) void k_conv(const float* __restrict__ mask) {
    int b  = blockIdx.y;
    int n0 = blockIdx.x * 128;
    __shared__ __align__(16) float As[16][128];
    __shared__ __align__(16) float Bs[16][128];
    int tid = threadIdx.x;
    int tx = tid & 15, ty = tid >> 4;
    float acc[8][8];
    #pragma unroll
    for (int i = 0; i < 8; ++i)
        #pragma unroll
        for (int j = 0; j < 8; ++j) acc[i][j] = 0.f;

    for (int k0 = 0; k0 < 3*IN_DIM_; k0 += 16) {
        int h  = k0 / IN_DIM_;
        int i0 = k0 % IN_DIM_;
        // load A tile [128 rows, 16 k], masked + tap-shifted
        #pragma unroll
        for (int p = 0; p < 2; ++p) {
            int r  = (tid >> 2) + p*64;      // t within batch
            int kk = (tid & 3) * 4;
            int tp = r + h - 1;
            float4 v = make_float4(0.f, 0.f, 0.f, 0.f);
            if (tp >= 0 && tp < T_) {
                v = *(const float4*)&g_inp[(b*T_ + tp)*IN_DIM_ + i0 + kk];
                float mv = mask[b*T_ + tp];
                v.x *= mv; v.y *= mv; v.z *= mv; v.w *= mv;
            }
            As[kk+0][r] = v.x; As[kk+1][r] = v.y; As[kk+2][r] = v.z; As[kk+3][r] = v.w;
        }
        // load B tile [16 k, 128 n]
        #pragma unroll
        for (int p = 0; p < 2; ++p) {
            int kk = (tid >> 5) + p*8;
            int nn = (tid & 31) * 4;
            float4 wv = *(const float4*)&g_Wt[(k0+kk)*NF_ + n0 + nn];
            *(float4*)&Bs[kk][nn] = wv;
        }
        __syncthreads();
        #pragma unroll
        for (int kk = 0; kk < 16; ++kk) {
            float4 a0 = *(float4*)&As[kk][ty*8];
            float4 a1 = *(float4*)&As[kk][ty*8 + 4];
            float4 b0 = *(float4*)&Bs[kk][tx*8];
            float4 b1 = *(float4*)&Bs[kk][tx*8 + 4];
            float av[8] = {a0.x,a0.y,a0.z,a0.w,a1.x,a1.y,a1.z,a1.w};
            float bv[8] = {b0.x,b0.y,b0.z,b0.w,b1.x,b1.y,b1.z,b1.w};
            #pragma unroll
            for (int i = 0; i < 8; ++i)
                #pragma unroll
                for (int j = 0; j < 8; ++j)
                    acc[i][j] += av[i] * bv[j];
        }
        __syncthreads();
    }
    // fused max over t (rows)
    float cmax[8];
    #pragma unroll
    for (int j = 0; j < 8; ++j) {
        float m = acc[0][j];
        #pragma unroll
        for (int i = 1; i < 8; ++i) m = fmaxf(m, acc[i][j]);
        cmax[j] = m;
    }
    #pragma unroll
    for (int j = 0; j < 8; ++j) As[ty][tx*8 + j] = cmax[j];
    __syncthreads();
    if (tid < 128) {
        float m = As[0][tid];
        #pragma unroll
        for (int y = 1; y < 16; ++y) m = fmaxf(m, As[y][tid]);
        g_cnnmax[b*NF_ + n0 + tid] = m;
    }
}

// ---------------- attention GEMM: per block = one batch, full N loop fused ----------------
// scores[b,t] = sum_e wr[e] * tanh( inp[b,t,:400].WaT[:,e] + c[b,e] ), then mask->NEG
__global__ __launch_bounds__(256) void k_attn(const float* __restrict__ wr1,
                                              const float* __restrict__ wr2,
                                              const float* __restrict__ mask) {
    int b = blockIdx.x, w = blockIdx.y;
    const float* WaT = g_WaT[w];
    const float* wr  = w ? wr2 : wr1;
    const float* cb  = &g_c[w][b*ATTN_];
    __shared__ __align__(16) float As[16][128];
    __shared__ __align__(16) float Bs[16][128];
    __shared__ float cs[128], wrs[128];
    int tid = threadIdx.x;
    int tx = tid & 15, ty = tid >> 4;
    float rowpart[8];
    #pragma unroll
    for (int i = 0; i < 8; ++i) rowpart[i] = 0.f;

    for (int n0 = 0; n0 < ATTN_; n0 += 128) {
        __syncthreads();   // protect cs/wrs from prior epilogue readers
        if (tid < 128) {
            int n = n0 + tid;
            cs[tid]  = (n < ATTN_) ? cb[n] : 0.f;
            wrs[tid] = (n < ATTN_) ? wr[n] : 0.f;
        }
        float acc[8][8];
        #pragma unroll
        for (int i = 0; i < 8; ++i)
            #pragma unroll
            for (int j = 0; j < 8; ++j) acc[i][j] = 0.f;

        for (int k0 = 0; k0 < IN_DIM_; k0 += 16) {
            #pragma unroll
            for (int p = 0; p < 2; ++p) {
                int r  = (tid >> 2) + p*64;
                int kk = (tid & 3) * 4;
                float4 v = *(const float4*)&g_inp[(b*T_ + r)*IN_DIM_ + k0 + kk];
                As[kk+0][r] = v.x; As[kk+1][r] = v.y; As[kk+2][r] = v.z; As[kk+3][r] = v.w;
            }
            #pragma unroll
            for (int p = 0; p < 2; ++p) {
                int kk = (tid >> 5) + p*8;
                int nn = (tid & 31) * 4;
                int n  = n0 + nn;
                if (n + 3 < ATTN_) {
                    float4 wv = *(const float4*)&WaT[(k0+kk)*ATTN_ + n];
                    *(float4*)&Bs[kk][nn] = wv;
                } else {
                    #pragma unroll
                    for (int j = 0; j < 4; ++j)
                        Bs[kk][nn+j] = (n + j < ATTN_) ? WaT[(k0+kk)*ATTN_ + n + j] : 0.f;
                }
            }
            __syncthreads();
            #pragma unroll
            for (int kk = 0; kk < 16; ++kk) {
                float4 a0 = *(float4*)&As[kk][ty*8];
                float4 a1 = *(float4*)&As[kk][ty*8 + 4];
                float4 b0 = *(float4*)&Bs[kk][tx*8];
                float4 b1 = *(float4*)&Bs[kk][tx*8 + 4];
                float av[8] = {a0.x,a0.y,a0.z,a0.w,a1.x,a1.y,a1.z,a1.w};
                float bv[8] = {b0.x,b0.y,b0.z,b0.w,b1.x,b1.y,b1.z,b1.w};
                #pragma unroll
                for (int i = 0; i < 8; ++i)
                    #pragma unroll
                    for (int j = 0; j < 8; ++j)
                        acc[i][j] += av[i] * bv[j];
            }
            __syncthreads();
        }
        // fused epilogue: tanh + wr dot, reduce over this n-chunk's cols
        #pragma unroll
        for (int i = 0; i < 8; ++i) {
            float rp = 0.f;
            #pragma unroll
            for (int j = 0; j < 8; ++j) {
                int col = tx*8 + j;
                rp += wrs[col] * tanhf(acc[i][j] + cs[col]);
            }
            rowpart[i] += rp;
        }
    }
    // reduce rowparts across the 16 tx lanes per row
    __syncthreads();
    float* red = &As[0][0];   // 2048 floats, exactly fits
    #pragma unroll
    for (int i = 0; i < 8; ++i) red[(ty*8 + i)*16 + tx] = rowpart[i];
    __syncthreads();
    if (tid < 128) {
        float s = 0.f;
        #pragma unroll
        for (int x = 0; x < 16; ++x) s += red[tid*16 + x];
        float mv = mask[b*T_ + tid];
        g_scores[w][b*T_ + tid] = (mv == 0.f) ? -1e30f : s;
    }
}

// ---------------- softmax over T ----------------
__global__ void k_softmax() {
    int b = blockIdx.x, w = blockIdx.y;
    int t = threadIdx.x;
    __shared__ float sh[128];
    float s = g_scores[w][b*T_ + t];
    sh[t] = s;
    __syncthreads();
    for (int o = 64; o > 0; o >>= 1) {
        if (t < o) sh[t] = fmaxf(sh[t], sh[t + o]);
        __syncthreads();
    }
    float mx = sh[0];
    __syncthreads();
    float e = expf(s - mx);
    sh[t] = e;
    __syncthreads();
    for (int o = 64; o > 0; o >>= 1) {
        if (t < o) sh[t] += sh[t + o];
        __syncthreads();
    }
    g_a[w][b*T_ + t] = e / sh[0];
}

// ---------------- weighted sums v1,v2 (single pass over inp) ----------------
__global__ void k_wsum() {
    int b = blockIdx.x;
    int tid = threadIdx.x;   // 512 threads
    __shared__ float a1s[128], a2s[128];
    if (tid < 128) {
        a1s[tid] = g_a[0][b*T_ + tid];
        a2s[tid] = g_a[1][b*T_ + tid];
    }
    __syncthreads();
    if (tid < IN_DIM_) {
        float s1 = 0.f, s2 = 0.f;
        #pragma unroll 4
        for (int t = 0; t < T_; ++t) {
            float x = g_inp[(b*T_ + t)*IN_DIM_ + tid];
            s1 += a1s[t] * x;
            s2 += a2s[t] * x;
        }
        g_v[0][b*IN_DIM_ + tid] = s1;
        g_v[1][b*IN_DIM_ + tid] = s2;
    }
}

// ---------------- final dense + softmax (cnn bias+tanh folded in) ----------------
__global__ void k_final(const float* __restrict__ conv_b,
                        const float* __restrict__ dw,
                        const float* __restrict__ db,
                        float* __restrict__ out) {
    int b = blockIdx.x;
    int tid = threadIdx.x;   // 128
    float part[NCLS_];
    #pragma unroll
    for (int c = 0; c < NCLS_; ++c) part[c] = 0.f;
    for (int idx = tid; idx < FEAT_; idx += 128) {
        float f;
        if (idx < NF_)                 f = tanhf(g_cnnmax[b*NF_ + idx] + conv_b[idx]);
        else if (idx < NF_ + IN_DIM_)  f = g_v[0][b*IN_DIM_ + (idx - NF_)];
        else                           f = g_v[1][b*IN_DIM_ + (idx - NF_ - IN_DIM_)];
        #pragma unroll
        for (int c = 0; c < NCLS_; ++c) part[c] += f * dw[c*FEAT_ + idx];
    }
    __shared__ float sred[128];
    __shared__ float lg[NCLS_];
    for (int c = 0; c < NCLS_; ++c) {
        sred[tid] = part[c];
        __syncthreads();
        for (int o = 64; o > 0; o >>= 1) {
            if (tid < o) sred[tid] += sred[tid + o];
            __syncthreads();
        }
        if (tid == 0) lg[c] = sred[0] + db[c];
        __syncthreads();
    }
    if (tid == 0) {
        float mx = lg[0];
        #pragma unroll
        for (int c = 1; c < NCLS_; ++c) mx = fmaxf(mx, lg[c]);
        float sm = 0.f;
        float e[NCLS_];
        #pragma unroll
        for (int c = 0; c < NCLS_; ++c) { e[c] = expf(lg[c] - mx); sm += e[c]; }
        #pragma unroll
        for (int c = 0; c < NCLS_; ++c) out[b*NCLS_ + c] = e[c] / sm;
    }
}

// ---------------- launch ----------------
extern "C" void kernel_launch(void* const* d_in, const int* in_sizes, int n_in,
                              void* d_out, int out_size) {
    const int*   words  = (const int*)d_in[0];
    const float* mask   = (const float*)d_in[1];
    const int*   d1i    = (const int*)d_in[2];
    const int*   d2i    = (const int*)d_in[3];
    // d_in[4..6] = piece masks (unused by reference eval path)
    const int*   arg1   = (const int*)d_in[7];
    const int*   arg2   = (const int*)d_in[8];
    const float* wemb   = (const float*)d_in[9];
    const float* d1e    = (const float*)d_in[10];
    const float* d2e    = (const float*)d_in[11];
    const float* Wa1    = (const float*)d_in[12];
    const float* wr1    = (const float*)d_in[13];
    const float* Wa2    = (const float*)d_in[14];
    const float* wr2    = (const float*)d_in[15];
    const float* conv_w = (const float*)d_in[16];
    const float* conv_b = (const float*)d_in[17];
    const float* dw     = (const float*)d_in[18];
    const float* db     = (const float*)d_in[19];
    float* out = (float*)d_out;

    const int NPREP = 3*IN_DIM_*NF_ + 2*IN_DIM_*ATTN_;   // 1,174,400
    k_prep<<<(NPREP + 255)/256, 256>>>(conv_w, Wa1, Wa2);
    k_gather<<<(M_*IN_DIM_ + 255)/256, 256>>>(words, d1i, d2i, wemb, d1e, d2e);
    k_argc<<<dim3(B_, 2), 256>>>(arg1, arg2, wemb, Wa1, Wa2);
    k_conv<<<dim3(NF_/128, B_), 256>>>(mask);
    k_attn<<<dim3(B_, 2), 256>>>(wr1, wr2, mask);
    k_softmax<<<dim3(B_, 2), 128>>>();
    k_wsum<<<B_, 512>>>();
    k_final<<<B_, 128>>>(conv_b, db ? dw : dw, db, out);
}

// round 2
// speedup vs baseline: 2.0383x; 2.0383x over previous
#include <cuda_runtime.h>
#include <math.h>
#include <stdint.h>

#define B_    256
#define T_    128
#define WD_   300
#define DD_   50
#define IN_DIM_ 400
#define ATTN_ 700
#define NF_   512
#define NCLS_ 19
#define M_    (B_*T_)
#define FEAT_ (NF_ + 2*IN_DIM_)
#define LDT   136   // padded smem row stride (words): banks (8t+g) conflict-free

// ---------------- scratch ----------------
__device__ float g_inp[M_*IN_DIM_];
__device__ float g_Wt[3*IN_DIM_*NF_];        // conv weights [h][i][o]
__device__ float g_WaT[2][IN_DIM_*ATTN_];    // Wa[:, :400]^T -> [i][e]
__device__ float g_c[2][B_*ATTN_];
__device__ float g_a[2][B_*T_];
__device__ float g_cnnmax[B_*NF_];
__device__ float g_v[2][B_*IN_DIM_];

__device__ __forceinline__ uint32_t f2tf32(float x) {
    uint32_t u;
    asm("cvt.rna.tf32.f32 %0, %1;" : "=r"(u) : "f"(x));
    return u;
}

#define MMA_TF32(c, a, b) \
    asm volatile("mma.sync.aligned.m16n8k8.row.col.f32.tf32.tf32.f32 " \
        "{%0,%1,%2,%3},{%4,%5,%6,%7},{%8,%9},{%0,%1,%2,%3};" \
        : "+f"(c[0]), "+f"(c[1]), "+f"(c[2]), "+f"(c[3]) \
        : "r"(a[0]), "r"(a[1]), "r"(a[2]), "r"(a[3]), "r"(b[0]), "r"(b[1]))

// ---------------- weight prep ----------------
__global__ void k_prep(const float* __restrict__ conv_w,
                       const float* __restrict__ Wa1,
                       const float* __restrict__ Wa2) {
    int idx = blockIdx.x * blockDim.x + threadIdx.x;
    const int NWT = 3*IN_DIM_*NF_;
    const int NWA = IN_DIM_*ATTN_;
    if (idx < NWT) {
        int h = idx / (IN_DIM_*NF_);
        int rem = idx % (IN_DIM_*NF_);
        int i = rem / NF_, o = rem % NF_;
        g_Wt[idx] = conv_w[o*(IN_DIM_*3) + i*3 + h];
    } else if (idx < NWT + 2*NWA) {
        int j = idx - NWT;
        int w = j / NWA;
        int r = j % NWA;
        int i = r / ATTN_, e = r % ATTN_;
        const float* Wa = w ? Wa2 : Wa1;
        g_WaT[w][r] = Wa[e*ATTN_ + i];
    }
}

// ---------------- gather ----------------
__global__ void k_gather(const int* __restrict__ words,
                         const int* __restrict__ d1i,
                         const int* __restrict__ d2i,
                         const float* __restrict__ wemb,
                         const float* __restrict__ d1e,
                         const float* __restrict__ d2e) {
    int idx = blockIdx.x * blockDim.x + threadIdx.x;
    if (idx >= M_*IN_DIM_) return;
    int m = idx / IN_DIM_, d = idx % IN_DIM_;
    float v;
    if (d < WD_)            v = wemb[words[m]*WD_ + d];
    else if (d < WD_+DD_)   v = d1e[d1i[m]*DD_ + (d - WD_)];
    else                    v = d2e[d2i[m]*DD_ + (d - WD_ - DD_)];
    g_inp[idx] = v;
}

// ---------------- c[b,e] = arg_emb . Wa[e,400:700] ----------------
__global__ void k_argc(const int* __restrict__ arg1,
                       const int* __restrict__ arg2,
                       const float* __restrict__ wemb,
                       const float* __restrict__ Wa1,
                       const float* __restrict__ Wa2) {
    int b = blockIdx.x, w = blockIdx.y;
    const int* arg = w ? arg2 : arg1;
    const float* Wa = w ? Wa2 : Wa1;
    __shared__ float ae[WD_];
    int aidx = arg[b];
    for (int d = threadIdx.x; d < WD_; d += blockDim.x)
        ae[d] = wemb[aidx*WD_ + d];
    __syncthreads();
    for (int e = threadIdx.x; e < ATTN_; e += blockDim.x) {
        const float* row = Wa + e*ATTN_ + IN_DIM_;
        float s = 0.f;
        #pragma unroll 4
        for (int d = 0; d < WD_; ++d) s += ae[d] * row[d];
        g_c[w][b*ATTN_ + e] = s;
    }
}

// ---------------- conv GEMM (tf32 mma) + fused time-max ----------------
__global__ __launch_bounds__(256) void k_conv(const float* __restrict__ mask) {
    int b  = blockIdx.y;
    int n0 = blockIdx.x * 128;
    __shared__ float As[16*LDT];
    __shared__ float Bs[16*LDT];
    __shared__ float smax[2][128];
    int tid = threadIdx.x;
    int lane = tid & 31, warp = tid >> 5;
    int warpM = warp & 1, warpN = warp >> 1;
    int g = lane >> 2, t = lane & 3;

    float acc[4][4][4];
    #pragma unroll
    for (int mi = 0; mi < 4; ++mi)
        #pragma unroll
        for (int ni = 0; ni < 4; ++ni)
            #pragma unroll
            for (int c = 0; c < 4; ++c) acc[mi][ni][c] = 0.f;

    for (int k0 = 0; k0 < 3*IN_DIM_; k0 += 16) {
        int h  = k0 / IN_DIM_;
        int i0 = k0 % IN_DIM_;
        // A tile [16 k][128 t], masked + tap-shifted, tf32-converted
        #pragma unroll
        for (int p = 0; p < 2; ++p) {
            int r  = (tid >> 2) + p*64;
            int kk = (tid & 3) * 4;
            int tp = r + h - 1;
            float4 v = make_float4(0.f, 0.f, 0.f, 0.f);
            if (tp >= 0 && tp < T_) {
                v = *(const float4*)&g_inp[(b*T_ + tp)*IN_DIM_ + i0 + kk];
                float mv = mask[b*T_ + tp];
                v.x *= mv; v.y *= mv; v.z *= mv; v.w *= mv;
            }
            As[(kk+0)*LDT + r] = __uint_as_float(f2tf32(v.x));
            As[(kk+1)*LDT + r] = __uint_as_float(f2tf32(v.y));
            As[(kk+2)*LDT + r] = __uint_as_float(f2tf32(v.z));
            As[(kk+3)*LDT + r] = __uint_as_float(f2tf32(v.w));
        }
        // B tile [16 k][128 n]
        #pragma unroll
        for (int p = 0; p < 2; ++p) {
            int kk = (tid >> 5) + p*8;
            int nn = (tid & 31) * 4;
            float4 wv = *(const float4*)&g_Wt[(k0+kk)*NF_ + n0 + nn];
            Bs[kk*LDT + nn+0] = __uint_as_float(f2tf32(wv.x));
            Bs[kk*LDT + nn+1] = __uint_as_float(f2tf32(wv.y));
            Bs[kk*LDT + nn+2] = __uint_as_float(f2tf32(wv.z));
            Bs[kk*LDT + nn+3] = __uint_as_float(f2tf32(wv.w));
        }
        __syncthreads();
        #pragma unroll
        for (int ks = 0; ks < 2; ++ks) {
            int kb = ks * 8;
            uint32_t af[4][4], bf[4][2];
            #pragma unroll
            for (int mi = 0; mi < 4; ++mi) {
                int rm = warpM*64 + mi*16;
                af[mi][0] = __float_as_uint(As[(kb+t  )*LDT + rm + g    ]);
                af[mi][1] = __float_as_uint(As[(kb+t  )*LDT + rm + g + 8]);
                af[mi][2] = __float_as_uint(As[(kb+t+4)*LDT + rm + g    ]);
                af[mi][3] = __float_as_uint(As[(kb+t+4)*LDT + rm + g + 8]);
            }
            #pragma unroll
            for (int ni = 0; ni < 4; ++ni) {
                int cn = warpN*32 + ni*8;
                bf[ni][0] = __float_as_uint(Bs[(kb+t  )*LDT + cn + g]);
                bf[ni][1] = __float_as_uint(Bs[(kb+t+4)*LDT + cn + g]);
            }
            #pragma unroll
            for (int mi = 0; mi < 4; ++mi)
                #pragma unroll
                for (int ni = 0; ni < 4; ++ni)
                    MMA_TF32(acc[mi][ni], af[mi], bf[ni]);
        }
        __syncthreads();
    }
    // fused max over t (rows): thread-local, then across g-lanes, then m-warps
    float cm[4][2];
    #pragma unroll
    for (int ni = 0; ni < 4; ++ni) { cm[ni][0] = -1e30f; cm[ni][1] = -1e30f; }
    #pragma unroll
    for (int mi = 0; mi < 4; ++mi)
        #pragma unroll
        for (int ni = 0; ni < 4; ++ni) {
            cm[ni][0] = fmaxf(cm[ni][0], fmaxf(acc[mi][ni][0], acc[mi][ni][2]));
            cm[ni][1] = fmaxf(cm[ni][1], fmaxf(acc[mi][ni][1], acc[mi][ni][3]));
        }
    #pragma unroll
    for (int off = 4; off < 32; off <<= 1)
        #pragma unroll
        for (int ni = 0; ni < 4; ++ni) {
            cm[ni][0] = fmaxf(cm[ni][0], __shfl_xor_sync(0xffffffffu, cm[ni][0], off));
            cm[ni][1] = fmaxf(cm[ni][1], __shfl_xor_sync(0xffffffffu, cm[ni][1], off));
        }
    if (g == 0) {
        #pragma unroll
        for (int ni = 0; ni < 4; ++ni) {
            int col = warpN*32 + ni*8 + 2*t;
            smax[warpM][col]   = cm[ni][0];
            smax[warpM][col+1] = cm[ni][1];
        }
    }
    __syncthreads();
    if (tid < 128)
        g_cnnmax[b*NF_ + n0 + tid] = fmaxf(smax[0][tid], smax[1][tid]);
}

// ---------------- attention GEMM (tf32 mma) + fused tanh.wr + softmax ----------------
__global__ __launch_bounds__(256) void k_attn(const float* __restrict__ wr1,
                                              const float* __restrict__ wr2,
                                              const float* __restrict__ mask) {
    int b = blockIdx.x, w = blockIdx.y;
    const float* WaT = g_WaT[w];
    const float* wr  = w ? wr2 : wr1;
    const float* cb  = &g_c[w][b*ATTN_];
    __shared__ float As[16*LDT];
    __shared__ float Bs[16*LDT];
    __shared__ float cs[128], wrs[128];
    __shared__ float red[4][128];
    __shared__ float sh[128];
    int tid = threadIdx.x;
    int lane = tid & 31, warp = tid >> 5;
    int warpM = warp & 1, warpN = warp >> 1;
    int g = lane >> 2, t = lane & 3;

    float rowacc[4][2];
    #pragma unroll
    for (int mi = 0; mi < 4; ++mi) { rowacc[mi][0] = 0.f; rowacc[mi][1] = 0.f; }

    for (int n0 = 0; n0 < ATTN_; n0 += 128) {
        __syncthreads();
        if (tid < 128) {
            int n = n0 + tid;
            cs[tid]  = (n < ATTN_) ? cb[n] : 0.f;
            wrs[tid] = (n < ATTN_) ? wr[n] : 0.f;
        }
        float acc[4][4][4];
        #pragma unroll
        for (int mi = 0; mi < 4; ++mi)
            #pragma unroll
            for (int ni = 0; ni < 4; ++ni)
                #pragma unroll
                for (int c = 0; c < 4; ++c) acc[mi][ni][c] = 0.f;

        for (int k0 = 0; k0 < IN_DIM_; k0 += 16) {
            #pragma unroll
            for (int p = 0; p < 2; ++p) {
                int r  = (tid >> 2) + p*64;
                int kk = (tid & 3) * 4;
                float4 v = *(const float4*)&g_inp[(b*T_ + r)*IN_DIM_ + k0 + kk];
                As[(kk+0)*LDT + r] = __uint_as_float(f2tf32(v.x));
                As[(kk+1)*LDT + r] = __uint_as_float(f2tf32(v.y));
                As[(kk+2)*LDT + r] = __uint_as_float(f2tf32(v.z));
                As[(kk+3)*LDT + r] = __uint_as_float(f2tf32(v.w));
            }
            #pragma unroll
            for (int p = 0; p < 2; ++p) {
                int kk = (tid >> 5) + p*8;
                int nn = (tid & 31) * 4;
                int n  = n0 + nn;
                if (n + 3 < ATTN_) {
                    float4 wv = *(const float4*)&WaT[(k0+kk)*ATTN_ + n];
                    Bs[kk*LDT + nn+0] = __uint_as_float(f2tf32(wv.x));
                    Bs[kk*LDT + nn+1] = __uint_as_float(f2tf32(wv.y));
                    Bs[kk*LDT + nn+2] = __uint_as_float(f2tf32(wv.z));
                    Bs[kk*LDT + nn+3] = __uint_as_float(f2tf32(wv.w));
                } else {
                    #pragma unroll
                    for (int j = 0; j < 4; ++j) {
                        float x = (n + j < ATTN_) ? WaT[(k0+kk)*ATTN_ + n + j] : 0.f;
                        Bs[kk*LDT + nn+j] = __uint_as_float(f2tf32(x));
                    }
                }
            }
            __syncthreads();
            #pragma unroll
            for (int ks = 0; ks < 2; ++ks) {
                int kb = ks * 8;
                uint32_t af[4][4], bf[4][2];
                #pragma unroll
                for (int mi = 0; mi < 4; ++mi) {
                    int rm = warpM*64 + mi*16;
                    af[mi][0] = __float_as_uint(As[(kb+t  )*LDT + rm + g    ]);
                    af[mi][1] = __float_as_uint(As[(kb+t  )*LDT + rm + g + 8]);
                    af[mi][2] = __float_as_uint(As[(kb+t+4)*LDT + rm + g    ]);
                    af[mi][3] = __float_as_uint(As[(kb+t+4)*LDT + rm + g + 8]);
                }
                #pragma unroll
                for (int ni = 0; ni < 4; ++ni) {
                    int cn = warpN*32 + ni*8;
                    bf[ni][0] = __float_as_uint(Bs[(kb+t  )*LDT + cn + g]);
                    bf[ni][1] = __float_as_uint(Bs[(kb+t+4)*LDT + cn + g]);
                }
                #pragma unroll
                for (int mi = 0; mi < 4; ++mi)
                    #pragma unroll
                    for (int ni = 0; ni < 4; ++ni)
                        MMA_TF32(acc[mi][ni], af[mi], bf[ni]);
            }
            __syncthreads();
        }
        // fused epilogue: tanh + wr dot over this 128-col chunk
        #pragma unroll
        for (int mi = 0; mi < 4; ++mi)
            #pragma unroll
            for (int rr = 0; rr < 2; ++rr) {
                float rp = 0.f;
                #pragma unroll
                for (int ni = 0; ni < 4; ++ni)
                    #pragma unroll
                    for (int c = 0; c < 2; ++c) {
                        int col = warpN*32 + ni*8 + 2*t + c;
                        rp += wrs[col] * tanhf(acc[mi][ni][rr*2 + c] + cs[col]);
                    }
                rowacc[mi][rr] += rp;
            }
    }
    // reduce across the 4 t-lanes (cols within group)
    #pragma unroll
    for (int off = 1; off < 4; off <<= 1)
        #pragma unroll
        for (int mi = 0; mi < 4; ++mi)
            #pragma unroll
            for (int rr = 0; rr < 2; ++rr)
                rowacc[mi][rr] += __shfl_xor_sync(0xffffffffu, rowacc[mi][rr], off);
    if (t == 0) {
        #pragma unroll
        for (int mi = 0; mi < 4; ++mi)
            #pragma unroll
            for (int rr = 0; rr < 2; ++rr) {
                int row = warpM*64 + mi*16 + g + rr*8;
                red[warpN][row] = rowacc[mi][rr];
            }
    }
    __syncthreads();
    // scores + in-block softmax, write attention weights
    float s = 0.f, e = 0.f;
    if (tid < 128) {
        s = red[0][tid] + red[1][tid] + red[2][tid] + red[3][tid];
        float mv = mask[b*T_ + tid];
        s = (mv == 0.f) ? -1e30f : s;
        sh[tid] = s;
    }
    __syncthreads();
    for (int o = 64; o > 0; o >>= 1) {
        if (tid < o) sh[tid] = fmaxf(sh[tid], sh[tid + o]);
        __syncthreads();
    }
    float mx = sh[0];
    __syncthreads();
    if (tid < 128) { e = expf(s - mx); sh[tid] = e; }
    __syncthreads();
    for (int o = 64; o > 0; o >>= 1) {
        if (tid < o) sh[tid] += sh[tid + o];
        __syncthreads();
    }
    if (tid < 128) g_a[w][b*T_ + tid] = e / sh[0];
}

// ---------------- weighted sums ----------------
__global__ void k_wsum() {
    int b = blockIdx.x;
    int tid = threadIdx.x;
    __shared__ float a1s[128], a2s[128];
    if (tid < 128) {
        a1s[tid] = g_a[0][b*T_ + tid];
        a2s[tid] = g_a[1][b*T_ + tid];
    }
    __syncthreads();
    if (tid < IN_DIM_) {
        float s1 = 0.f, s2 = 0.f;
        #pragma unroll 4
        for (int t = 0; t < T_; ++t) {
            float x = g_inp[(b*T_ + t)*IN_DIM_ + tid];
            s1 += a1s[t] * x;
            s2 += a2s[t] * x;
        }
        g_v[0][b*IN_DIM_ + tid] = s1;
        g_v[1][b*IN_DIM_ + tid] = s2;
    }
}

// ---------------- final dense + softmax ----------------
__global__ void k_final(const float* __restrict__ conv_b,
                        const float* __restrict__ dw,
                        const float* __restrict__ db,
                        float* __restrict__ out) {
    int b = blockIdx.x;
    int tid = threadIdx.x;
    float part[NCLS_];
    #pragma unroll
    for (int c = 0; c < NCLS_; ++c) part[c] = 0.f;
    for (int idx = tid; idx < FEAT_; idx += 128) {
        float f;
        if (idx < NF_)                 f = tanhf(g_cnnmax[b*NF_ + idx] + conv_b[idx]);
        else if (idx < NF_ + IN_DIM_)  f = g_v[0][b*IN_DIM_ + (idx - NF_)];
        else                           f = g_v[1][b*IN_DIM_ + (idx - NF_ - IN_DIM_)];
        #pragma unroll
        for (int c = 0; c < NCLS_; ++c) part[c] += f * dw[c*FEAT_ + idx];
    }
    __shared__ float sred[128];
    __shared__ float lg[NCLS_];
    for (int c = 0; c < NCLS_; ++c) {
        sred[tid] = part[c];
        __syncthreads();
        for (int o = 64; o > 0; o >>= 1) {
            if (tid < o) sred[tid] += sred[tid + o];
            __syncthreads();
        }
        if (tid == 0) lg[c] = sred[0] + db[c];
        __syncthreads();
    }
    if (tid == 0) {
        float mx = lg[0];
        #pragma unroll
        for (int c = 1; c < NCLS_; ++c) mx = fmaxf(mx, lg[c]);
        float sm = 0.f;
        float e[NCLS_];
        #pragma unroll
        for (int c = 0; c < NCLS_; ++c) { e[c] = expf(lg[c] - mx); sm += e[c]; }
        #pragma unroll
        for (int c = 0; c < NCLS_; ++c) out[b*NCLS_ + c] = e[c] / sm;
    }
}

// ---------------- launch ----------------
extern "C" void kernel_launch(void* const* d_in, const int* in_sizes, int n_in,
                              void* d_out, int out_size) {
    const int*   words  = (const int*)d_in[0];
    const float* mask   = (const float*)d_in[1];
    const int*   d1i    = (const int*)d_in[2];
    const int*   d2i    = (const int*)d_in[3];
    const int*   arg1   = (const int*)d_in[7];
    const int*   arg2   = (const int*)d_in[8];
    const float* wemb   = (const float*)d_in[9];
    const float* d1e    = (const float*)d_in[10];
    const float* d2e    = (const float*)d_in[11];
    const float* Wa1    = (const float*)d_in[12];
    const float* wr1    = (const float*)d_in[13];
    const float* Wa2    = (const float*)d_in[14];
    const float* wr2    = (const float*)d_in[15];
    const float* conv_w = (const float*)d_in[16];
    const float* conv_b = (const float*)d_in[17];
    const float* dw     = (const float*)d_in[18];
    const float* db     = (const float*)d_in[19];
    float* out = (float*)d_out;

    const int NPREP = 3*IN_DIM_*NF_ + 2*IN_DIM_*ATTN_;
    k_prep<<<(NPREP + 255)/256, 256>>>(conv_w, Wa1, Wa2);
    k_gather<<<(M_*IN_DIM_ + 255)/256, 256>>>(words, d1i, d2i, wemb, d1e, d2e);
    k_argc<<<dim3(B_, 2), 256>>>(arg1, arg2, wemb, Wa1, Wa2);
    k_conv<<<dim3(NF_/128, B_), 256>>>(mask);
    k_attn<<<dim3(B_, 2), 256>>>(wr1, wr2, mask);
    k_wsum<<<B_, 512>>>();
    k_final<<<B_, 128>>>(conv_b, dw, db, out);
}

// round 3
// speedup vs baseline: 2.2094x; 1.0840x over previous
#include <cuda_runtime.h>
#include <math.h>
#include <stdint.h>

#define B_    256
#define T_    128
#define WD_   300
#define DD_   50
#define IN_DIM_ 400
#define IN_PAD  416
#define ROWSP   130          // T_+2 padded rows
#define ATTN_ 700
#define NPADA 768            // padded attn N (6*128)
#define KC_   1216           // padded conv K (38*32)
#define KA_   416            // padded attn K (13*32)
#define NF_   512
#define NCLS_ 19
#define M_    (B_*T_)
#define FEAT_ (NF_ + 2*IN_DIM_)
#define LDA   36             // smem tile stride in words
#define TILE_W (128*LDA)     // 4608 words per tile
#define SMEM_BYTES (4*TILE_W*4)   // 73728

// ---------------- scratch ----------------
__device__ float g_inpm[B_*ROWSP*IN_PAD];    // masked, tf32-rounded, padded
__device__ float g_WtT[NF_*KC_];             // conv weights [o][k], k=h*400+i, tf32
__device__ float g_WaTp[2*NPADA*KA_];        // Wa[:, :400] as [e][i], padded, tf32
__device__ float g_c[2][B_*ATTN_];
__device__ float g_spart[2*6*M_];            // attn score partials per n-chunk
__device__ float g_a[2][B_*T_];
__device__ float g_cnnmax[B_*NF_];
__device__ float g_v[2][B_*IN_DIM_];

__device__ __forceinline__ uint32_t f2tf32(float x) {
    uint32_t u;
    asm("cvt.rna.tf32.f32 %0, %1;" : "=r"(u) : "f"(x));
    return u;
}
__device__ __forceinline__ float rtf32(float x) { return __uint_as_float(f2tf32(x)); }

__device__ __forceinline__ void cpa16(uint32_t dst, const void* src) {
    asm volatile("cp.async.cg.shared.global [%0], [%1], 16;\n" :: "r"(dst), "l"(src));
}
#define CP_COMMIT() asm volatile("cp.async.commit_group;\n")
#define CP_WAIT(n)  asm volatile("cp.async.wait_group %0;\n" :: "n"(n))

__device__ __forceinline__ void ldsm4(uint32_t* r, uint32_t a) {
    asm volatile("ldmatrix.sync.aligned.m8n8.x4.shared.b16 {%0,%1,%2,%3}, [%4];"
        : "=r"(r[0]), "=r"(r[1]), "=r"(r[2]), "=r"(r[3]) : "r"(a));
}
__device__ __forceinline__ void ldsm2(uint32_t* r, uint32_t a) {
    asm volatile("ldmatrix.sync.aligned.m8n8.x2.shared.b16 {%0,%1}, [%2];"
        : "=r"(r[0]), "=r"(r[1]) : "r"(a));
}

#define MMA_TF32(c, a, b) \
    asm volatile("mma.sync.aligned.m16n8k8.row.col.f32.tf32.tf32.f32 " \
        "{%0,%1,%2,%3},{%4,%5,%6,%7},{%8,%9},{%0,%1,%2,%3};" \
        : "+f"(c[0]), "+f"(c[1]), "+f"(c[2]), "+f"(c[3]) \
        : "r"(a[0]), "r"(a[1]), "r"(a[2]), "r"(a[3]), "r"(b[0]), "r"(b[1]))

// ---------------- weight prep: transposed + tf32-rounded + zero-padded ----------------
__global__ void k_prep(const float* __restrict__ conv_w,
                       const float* __restrict__ Wa1,
                       const float* __restrict__ Wa2) {
    int idx = blockIdx.x * blockDim.x + threadIdx.x;
    const int NWT = NF_*KC_;
    const int NWA = NPADA*KA_;
    if (idx < NWT) {
        int o = idx / KC_, k = idx % KC_;
        float v = 0.f;
        if (k < 1200) {
            int h = k / 400, i = k - h*400;
            v = rtf32(conv_w[o*1200 + i*3 + h]);
        }
        g_WtT[idx] = v;
    } else if (idx < NWT + 2*NWA) {
        int j = idx - NWT;
        int w = j / NWA;
        int r = j % NWA;
        int e = r / KA_, i = r % KA_;
        const float* Wa = w ? Wa2 : Wa1;
        float v = 0.f;
        if (e < ATTN_ && i < IN_DIM_) v = rtf32(Wa[e*ATTN_ + i]);
        g_WaTp[w*NWA + r] = v;
    }
}

// ---------------- gather: masked + rounded + padded ----------------
__global__ void k_gather(const int* __restrict__ words,
                         const int* __restrict__ d1i,
                         const int* __restrict__ d2i,
                         const float* __restrict__ wemb,
                         const float* __restrict__ d1e,
                         const float* __restrict__ d2e,
                         const float* __restrict__ mask) {
    int idx = blockIdx.x * blockDim.x + threadIdx.x;
    if (idx >= B_*ROWSP*IN_PAD) return;
    int i = idx % IN_PAD;
    int r = (idx / IN_PAD) % ROWSP;
    int b = idx / (IN_PAD*ROWSP);
    float v = 0.f;
    if (r >= 1 && r <= T_ && i < IN_DIM_) {
        int m = b*T_ + (r-1);
        float x;
        if (i < WD_)            x = wemb[words[m]*WD_ + i];
        else if (i < WD_+DD_)   x = d1e[d1i[m]*DD_ + (i - WD_)];
        else                    x = d2e[d2i[m]*DD_ + (i - WD_ - DD_)];
        v = rtf32(x) * mask[m];
    }
    g_inpm[idx] = v;
}

// ---------------- c[b,e] = arg_emb . Wa[e,400:700] ----------------
__global__ void k_argc(const int* __restrict__ arg1,
                       const int* __restrict__ arg2,
                       const float* __restrict__ wemb,
                       const float* __restrict__ Wa1,
                       const float* __restrict__ Wa2) {
    int b = blockIdx.x, w = blockIdx.y;
    const int* arg = w ? arg2 : arg1;
    const float* Wa = w ? Wa2 : Wa1;
    __shared__ float ae[WD_];
    int aidx = arg[b];
    for (int d = threadIdx.x; d < WD_; d += blockDim.x)
        ae[d] = wemb[aidx*WD_ + d];
    __syncthreads();
    for (int e = threadIdx.x; e < ATTN_; e += blockDim.x) {
        const float* row = Wa + e*ATTN_ + IN_DIM_;
        float s = 0.f;
        #pragma unroll 4
        for (int d = 0; d < WD_; ++d) s += ae[d] * row[d];
        g_c[w][b*ATTN_ + e] = s;
    }
}

// ---------------- conv GEMM: double-buffered cp.async + ldmatrix + fused time-max ----------------
__global__ __launch_bounds__(256, 2) void k_conv() {
    int b  = blockIdx.y;
    int n0 = blockIdx.x * 128;
    extern __shared__ float smem[];
    uint32_t sb = (uint32_t)__cvta_generic_to_shared(smem);
    uint32_t abuf[2] = { sb,              sb + TILE_W*4 };
    uint32_t bbuf[2] = { sb + 2*TILE_W*4, sb + 3*TILE_W*4 };

    int tid = threadIdx.x;
    int lane = tid & 31, warp = tid >> 5;
    int warpM = warp & 1, warpN = warp >> 1;

    int lr = tid >> 1;            // loader row 0..127
    int jb = (tid & 1) * 4;       // loader 16B-group base

    float acc[4][4][4];
    #pragma unroll
    for (int mi = 0; mi < 4; ++mi)
        #pragma unroll
        for (int ni = 0; ni < 4; ++ni)
            #pragma unroll
            for (int c = 0; c < 4; ++c) acc[mi][ni][c] = 0.f;

    const int NT = KC_/32;   // 38

    // tile loader
    auto load_tile = [&](int kt, int d) {
        int k0 = kt * 32;
        #pragma unroll
        for (int j = 0; j < 4; ++j) {
            int k = k0 + (jb + j) * 4;
            int h, i;
            if (k < 1200) { h = k / 400; i = k - h*400; }
            else          { h = 0;       i = k - 800; }      // zero pad cols
            cpa16(abuf[d] + (lr*LDA + (jb + j)*4)*4,
                  &g_inpm[(b*ROWSP + lr + h)*IN_PAD + i]);
        }
        #pragma unroll
        for (int j = 0; j < 4; ++j) {
            int k = k0 + (jb + j) * 4;
            cpa16(bbuf[d] + (lr*LDA + (jb + j)*4)*4,
                  &g_WtT[(n0 + lr)*KC_ + k]);
        }
        CP_COMMIT();
    };

    load_tile(0, 0);
    for (int kt = 0; kt < NT; ++kt) {
        int d = kt & 1;
        if (kt + 1 < NT) { load_tile(kt + 1, d ^ 1); CP_WAIT(1); }
        else             { CP_WAIT(0); }
        __syncthreads();
        #pragma unroll
        for (int ks = 0; ks < 4; ++ks) {
            int kb = ks * 8;
            uint32_t af[4][4], bf[4][2];
            #pragma unroll
            for (int mi = 0; mi < 4; ++mi) {
                int row = warpM*64 + mi*16 + (lane & 7) + ((lane >> 3) & 1)*8;
                ldsm4(af[mi], abuf[d] + (row*LDA + kb + ((lane >> 4) << 2))*4);
            }
            #pragma unroll
            for (int ni = 0; ni < 4; ++ni) {
                int row = warpN*32 + ni*8 + (lane & 7);
                ldsm2(bf[ni], bbuf[d] + (row*LDA + kb + (((lane >> 3) & 1) << 2))*4);
            }
            #pragma unroll
            for (int mi = 0; mi < 4; ++mi)
                #pragma unroll
                for (int ni = 0; ni < 4; ++ni)
                    MMA_TF32(acc[mi][ni], af[mi], bf[ni]);
        }
        __syncthreads();
    }

    // fused max over t
    int g = lane >> 2, t = lane & 3;
    float cm[4][2];
    #pragma unroll
    for (int ni = 0; ni < 4; ++ni) { cm[ni][0] = -1e30f; cm[ni][1] = -1e30f; }
    #pragma unroll
    for (int mi = 0; mi < 4; ++mi)
        #pragma unroll
        for (int ni = 0; ni < 4; ++ni) {
            cm[ni][0] = fmaxf(cm[ni][0], fmaxf(acc[mi][ni][0], acc[mi][ni][2]));
            cm[ni][1] = fmaxf(cm[ni][1], fmaxf(acc[mi][ni][1], acc[mi][ni][3]));
        }
    #pragma unroll
    for (int off = 4; off < 32; off <<= 1)
        #pragma unroll
        for (int ni = 0; ni < 4; ++ni) {
            cm[ni][0] = fmaxf(cm[ni][0], __shfl_xor_sync(0xffffffffu, cm[ni][0], off));
            cm[ni][1] = fmaxf(cm[ni][1], __shfl_xor_sync(0xffffffffu, cm[ni][1], off));
        }
    float* smax = smem;   // alias [2][128], buffers dead
    if (g == 0) {
        #pragma unroll
        for (int ni = 0; ni < 4; ++ni) {
            int col = warpN*32 + ni*8 + 2*t;
            smax[warpM*128 + col]     = cm[ni][0];
            smax[warpM*128 + col + 1] = cm[ni][1];
        }
    }
    __syncthreads();
    if (tid < 128)
        g_cnnmax[b*NF_ + n0 + tid] = fmaxf(smax[tid], smax[128 + tid]);
}

// ---------------- attention GEMM: one n-chunk per block, partials out ----------------
__global__ __launch_bounds__(256, 2) void k_attn(const float* __restrict__ wr1,
                                                 const float* __restrict__ wr2) {
    int b = blockIdx.x, w = blockIdx.y;
    int chunk = blockIdx.z;
    int n0 = chunk * 128;
    const float* wr = w ? wr2 : wr1;
    const float* cb = &g_c[w][b*ATTN_];

    extern __shared__ float smem[];
    __shared__ float cs[128], wrs[128];
    uint32_t sb = (uint32_t)__cvta_generic_to_shared(smem);
    uint32_t abuf[2] = { sb,              sb + TILE_W*4 };
    uint32_t bbuf[2] = { sb + 2*TILE_W*4, sb + 3*TILE_W*4 };

    int tid = threadIdx.x;
    int lane = tid & 31, warp = tid >> 5;
    int warpM = warp & 1, warpN = warp >> 1;
    int g = lane >> 2, t = lane & 3;
    int lr = tid >> 1;
    int jb = (tid & 1) * 4;

    if (tid < 128) {
        int n = n0 + tid;
        cs[tid]  = (n < ATTN_) ? cb[n] : 0.f;
        wrs[tid] = (n < ATTN_) ? wr[n] : 0.f;
    }

    float acc[4][4][4];
    #pragma unroll
    for (int mi = 0; mi < 4; ++mi)
        #pragma unroll
        for (int ni = 0; ni < 4; ++ni)
            #pragma unroll
            for (int c = 0; c < 4; ++c) acc[mi][ni][c] = 0.f;

    const int NT = KA_/32;   // 13
    const float* Bsrc = &g_WaTp[w*NPADA*KA_];

    auto load_tile = [&](int kt, int d) {
        int k0 = kt * 32;
        #pragma unroll
        for (int j = 0; j < 4; ++j) {
            int k = k0 + (jb + j) * 4;
            cpa16(abuf[d] + (lr*LDA + (jb + j)*4)*4,
                  &g_inpm[(b*ROWSP + lr + 1)*IN_PAD + k]);
        }
        #pragma unroll
        for (int j = 0; j < 4; ++j) {
            int k = k0 + (jb + j) * 4;
            cpa16(bbuf[d] + (lr*LDA + (jb + j)*4)*4,
                  &Bsrc[(n0 + lr)*KA_ + k]);
        }
        CP_COMMIT();
    };

    load_tile(0, 0);
    for (int kt = 0; kt < NT; ++kt) {
        int d = kt & 1;
        if (kt + 1 < NT) { load_tile(kt + 1, d ^ 1); CP_WAIT(1); }
        else             { CP_WAIT(0); }
        __syncthreads();
        #pragma unroll
        for (int ks = 0; ks < 4; ++ks) {
            int kb = ks * 8;
            uint32_t af[4][4], bf[4][2];
            #pragma unroll
            for (int mi = 0; mi < 4; ++mi) {
                int row = warpM*64 + mi*16 + (lane & 7) + ((lane >> 3) & 1)*8;
                ldsm4(af[mi], abuf[d] + (row*LDA + kb + ((lane >> 4) << 2))*4);
            }
            #pragma unroll
            for (int ni = 0; ni < 4; ++ni) {
                int row = warpN*32 + ni*8 + (lane & 7);
                ldsm2(bf[ni], bbuf[d] + (row*LDA + kb + (((lane >> 3) & 1) << 2))*4);
            }
            #pragma unroll
            for (int mi = 0; mi < 4; ++mi)
                #pragma unroll
                for (int ni = 0; ni < 4; ++ni)
                    MMA_TF32(acc[mi][ni], af[mi], bf[ni]);
        }
        __syncthreads();
    }

    // epilogue: tanh + wr dot over this chunk, reduce to rows
    float rowacc[4][2];
    #pragma unroll
    for (int mi = 0; mi < 4; ++mi) {
        #pragma unroll
        for (int rr = 0; rr < 2; ++rr) {
            float rp = 0.f;
            #pragma unroll
            for (int ni = 0; ni < 4; ++ni)
                #pragma unroll
                for (int c = 0; c < 2; ++c) {
                    int col = warpN*32 + ni*8 + 2*t + c;
                    rp += wrs[col] * tanhf(acc[mi][ni][rr*2 + c] + cs[col]);
                }
            rowacc[mi][rr] = rp;
        }
    }
    #pragma unroll
    for (int off = 1; off < 4; off <<= 1)
        #pragma unroll
        for (int mi = 0; mi < 4; ++mi)
            #pragma unroll
            for (int rr = 0; rr < 2; ++rr)
                rowacc[mi][rr] += __shfl_xor_sync(0xffffffffu, rowacc[mi][rr], off);
    float* red = smem;   // alias [4][128]
    if (t == 0) {
        #pragma unroll
        for (int mi = 0; mi < 4; ++mi)
            #pragma unroll
            for (int rr = 0; rr < 2; ++rr) {
                int row = warpM*64 + mi*16 + g + rr*8;
                red[warpN*128 + row] = rowacc[mi][rr];
            }
    }
    __syncthreads();
    if (tid < 128) {
        float s = red[tid] + red[128 + tid] + red[256 + tid] + red[384 + tid];
        g_spart[(w*6 + chunk)*M_ + b*T_ + tid] = s;
    }
}

// ---------------- softmax over T (sums chunk partials) ----------------
__global__ void k_softmax(const float* __restrict__ mask) {
    int b = blockIdx.x, w = blockIdx.y;
    int t = threadIdx.x;
    __shared__ float sh[128];
    float s = 0.f;
    #pragma unroll
    for (int c = 0; c < 6; ++c) s += g_spart[(w*6 + c)*M_ + b*T_ + t];
    float mv = mask[b*T_ + t];
    s = (mv == 0.f) ? -1e30f : s;
    sh[t] = s;
    __syncthreads();
    for (int o = 64; o > 0; o >>= 1) {
        if (t < o) sh[t] = fmaxf(sh[t], sh[t + o]);
        __syncthreads();
    }
    float mx = sh[0];
    __syncthreads();
    float e = expf(s - mx);
    sh[t] = e;
    __syncthreads();
    for (int o = 64; o > 0; o >>= 1) {
        if (t < o) sh[t] += sh[t + o];
        __syncthreads();
    }
    g_a[w][b*T_ + t] = e / sh[0];
}

// ---------------- weighted sums ----------------
__global__ void k_wsum() {
    int b = blockIdx.x;
    int tid = threadIdx.x;
    __shared__ float a1s[128], a2s[128];
    if (tid < 128) {
        a1s[tid] = g_a[0][b*T_ + tid];
        a2s[tid] = g_a[1][b*T_ + tid];
    }
    __syncthreads();
    if (tid < IN_DIM_) {
        float s1 = 0.f, s2 = 0.f;
        #pragma unroll 4
        for (int t = 0; t < T_; ++t) {
            float x = g_inpm[(b*ROWSP + t + 1)*IN_PAD + tid];
            s1 += a1s[t] * x;
            s2 += a2s[t] * x;
        }
        g_v[0][b*IN_DIM_ + tid] = s1;
        g_v[1][b*IN_DIM_ + tid] = s2;
    }
}

// ---------------- final dense + softmax ----------------
__global__ void k_final(const float* __restrict__ conv_b,
                        const float* __restrict__ dw,
                        const float* __restrict__ db,
                        float* __restrict__ out) {
    int b = blockIdx.x;
    int tid = threadIdx.x;
    float part[NCLS_];
    #pragma unroll
    for (int c = 0; c < NCLS_; ++c) part[c] = 0.f;
    for (int idx = tid; idx < FEAT_; idx += 128) {
        float f;
        if (idx < NF_)                 f = tanhf(g_cnnmax[b*NF_ + idx] + conv_b[idx]);
        else if (idx < NF_ + IN_DIM_)  f = g_v[0][b*IN_DIM_ + (idx - NF_)];
        else                           f = g_v[1][b*IN_DIM_ + (idx - NF_ - IN_DIM_)];
        #pragma unroll
        for (int c = 0; c < NCLS_; ++c) part[c] += f * dw[c*FEAT_ + idx];
    }
    __shared__ float sred[128];
    __shared__ float lg[NCLS_];
    for (int c = 0; c < NCLS_; ++c) {
        sred[tid] = part[c];
        __syncthreads();
        for (int o = 64; o > 0; o >>= 1) {
            if (tid < o) sred[tid] += sred[tid + o];
            __syncthreads();
        }
        if (tid == 0) lg[c] = sred[0] + db[c];
        __syncthreads();
    }
    if (tid == 0) {
        float mx = lg[0];
        #pragma unroll
        for (int c = 1; c < NCLS_; ++c) mx = fmaxf(mx, lg[c]);
        float sm = 0.f;
        float e[NCLS_];
        #pragma unroll
        for (int c = 0; c < NCLS_; ++c) { e[c] = expf(lg[c] - mx); sm += e[c]; }
        #pragma unroll
        for (int c = 0; c < NCLS_; ++c) out[b*NCLS_ + c] = e[c] / sm;
    }
}

// ---------------- launch ----------------
extern "C" void kernel_launch(void* const* d_in, const int* in_sizes, int n_in,
                              void* d_out, int out_size) {
    const int*   words  = (const int*)d_in[0];
    const float* mask   = (const float*)d_in[1];
    const int*   d1i    = (const int*)d_in[2];
    const int*   d2i    = (const int*)d_in[3];
    const int*   arg1   = (const int*)d_in[7];
    const int*   arg2   = (const int*)d_in[8];
    const float* wemb   = (const float*)d_in[9];
    const float* d1e    = (const float*)d_in[10];
    const float* d2e    = (const float*)d_in[11];
    const float* Wa1    = (const float*)d_in[12];
    const float* wr1    = (const float*)d_in[13];
    const float* Wa2    = (const float*)d_in[14];
    const float* wr2    = (const float*)d_in[15];
    const float* conv_w = (const float*)d_in[16];
    const float* conv_b = (const float*)d_in[17];
    const float* dw     = (const float*)d_in[18];
    const float* db     = (const float*)d_in[19];
    float* out = (float*)d_out;

    cudaFuncSetAttribute(k_conv, cudaFuncAttributeMaxDynamicSharedMemorySize, SMEM_BYTES);
    cudaFuncSetAttribute(k_attn, cudaFuncAttributeMaxDynamicSharedMemorySize, SMEM_BYTES);

    const int NPREP = NF_*KC_ + 2*NPADA*KA_;
    k_prep<<<(NPREP + 255)/256, 256>>>(conv_w, Wa1, Wa2);
    k_gather<<<(B_*ROWSP*IN_PAD + 255)/256, 256>>>(words, d1i, d2i, wemb, d1e, d2e, mask);
    k_argc<<<dim3(B_, 2), 256>>>(arg1, arg2, wemb, Wa1, Wa2);
    k_conv<<<dim3(NF_/128, B_), 256, SMEM_BYTES>>>();
    k_attn<<<dim3(B_, 2, 6), 256, SMEM_BYTES>>>(wr1, wr2);
    k_softmax<<<dim3(B_, 2), 128>>>(mask);
    k_wsum<<<B_, 512>>>();
    k_final<<<B_, 128>>>(conv_b, dw, db, out);
}

// round 6
// speedup vs baseline: 3.0124x; 1.3635x over previous
#include <cuda_runtime.h>
#include <math.h>
#include <stdint.h>

#define B_    256
#define T_    128
#define WD_   300
#define DD_   50
#define IN_DIM_ 400
#define IN_PAD  416
#define ROWSP   130
#define ATTN_ 700
#define NPADA 768
#define KC_   1216
#define KA_   416
#define NF_   512
#define NCLS_ 19
#define M_    (B_*T_)
#define FEAT_ (NF_ + 2*IN_DIM_)
#define KT_   16
#define LDA   20              // smem row stride (words); conflict-free for ldmatrix
#define TILE_W (128*LDA)      // 2560 words per tile
#define NSTG  4
#define SMEM_BYTES (NSTG*2*TILE_W*4)   // 81920

// ---------------- scratch ----------------
__device__ float g_inpm[B_*ROWSP*IN_PAD];
__device__ float g_WtT[NF_*KC_];
__device__ float g_WaTp[2*NPADA*KA_];
__device__ float g_c[2][B_*ATTN_];
__device__ float g_spart[2*6*M_];
__device__ float g_cnnmax[B_*NF_];

__device__ __forceinline__ uint32_t f2tf32(float x) {
    uint32_t u;
    asm("cvt.rna.tf32.f32 %0, %1;" : "=r"(u) : "f"(x));
    return u;
}
__device__ __forceinline__ float rtf32(float x) { return __uint_as_float(f2tf32(x)); }

__device__ __forceinline__ void cpa16(uint32_t dst, const void* src) {
    asm volatile("cp.async.cg.shared.global [%0], [%1], 16;\n" :: "r"(dst), "l"(src));
}
#define CP_COMMIT() asm volatile("cp.async.commit_group;\n")
#define CP_WAIT(n)  asm volatile("cp.async.wait_group %0;\n" :: "n"(n))

__device__ __forceinline__ void ldsm4(uint32_t* r, uint32_t a) {
    asm volatile("ldmatrix.sync.aligned.m8n8.x4.shared.b16 {%0,%1,%2,%3}, [%4];"
        : "=r"(r[0]), "=r"(r[1]), "=r"(r[2]), "=r"(r[3]) : "r"(a));
}
__device__ __forceinline__ void ldsm2(uint32_t* r, uint32_t a) {
    asm volatile("ldmatrix.sync.aligned.m8n8.x2.shared.b16 {%0,%1}, [%2];"
        : "=r"(r[0]), "=r"(r[1]) : "r"(a));
}

#define MMA_TF32(c, a, b) \
    asm volatile("mma.sync.aligned.m16n8k8.row.col.f32.tf32.tf32.f32 " \
        "{%0,%1,%2,%3},{%4,%5,%6,%7},{%8,%9},{%0,%1,%2,%3};" \
        : "+f"(c[0]), "+f"(c[1]), "+f"(c[2]), "+f"(c[3]) \
        : "r"(a[0]), "r"(a[1]), "r"(a[2]), "r"(a[3]), "r"(b[0]), "r"(b[1]))

// ---------------- weight prep ----------------
__global__ void k_prep(const float* __restrict__ conv_w,
                       const float* __restrict__ Wa1,
                       const float* __restrict__ Wa2) {
    int idx = blockIdx.x * blockDim.x + threadIdx.x;
    const int NWT = NF_*KC_;
    const int NWA = NPADA*KA_;
    if (idx < NWT) {
        int o = idx / KC_, k = idx % KC_;
        float v = 0.f;
        if (k < 1200) {
            int h = k / 400, i = k - h*400;
            v = rtf32(conv_w[o*1200 + i*3 + h]);
        }
        g_WtT[idx] = v;
    } else if (idx < NWT + 2*NWA) {
        int j = idx - NWT;
        int w = j / NWA;
        int r = j % NWA;
        int e = r / KA_, i = r % KA_;
        const float* Wa = w ? Wa2 : Wa1;
        float v = 0.f;
        if (e < ATTN_ && i < IN_DIM_) v = rtf32(Wa[e*ATTN_ + i]);
        g_WaTp[w*NWA + r] = v;
    }
}

// ---------------- gather ----------------
__global__ void k_gather(const int* __restrict__ words,
                         const int* __restrict__ d1i,
                         const int* __restrict__ d2i,
                         const float* __restrict__ wemb,
                         const float* __restrict__ d1e,
                         const float* __restrict__ d2e,
                         const float* __restrict__ mask) {
    int idx = blockIdx.x * blockDim.x + threadIdx.x;
    if (idx >= B_*ROWSP*IN_PAD) return;
    int i = idx % IN_PAD;
    int r = (idx / IN_PAD) % ROWSP;
    int b = idx / (IN_PAD*ROWSP);
    float v = 0.f;
    if (r >= 1 && r <= T_ && i < IN_DIM_) {
        int m = b*T_ + (r-1);
        float x;
        if (i < WD_)            x = wemb[words[m]*WD_ + i];
        else if (i < WD_+DD_)   x = d1e[d1i[m]*DD_ + (i - WD_)];
        else                    x = d2e[d2i[m]*DD_ + (i - WD_ - DD_)];
        v = rtf32(x) * mask[m];
    }
    g_inpm[idx] = v;
}

// ---------------- c[b,e]: coalesced warp-per-row ----------------
__global__ void k_argc(const int* __restrict__ arg1,
                       const int* __restrict__ arg2,
                       const float* __restrict__ wemb,
                       const float* __restrict__ Wa1,
                       const float* __restrict__ Wa2) {
    int b = blockIdx.x, w = blockIdx.y;
    const int* arg = w ? arg2 : arg1;
    const float* Wa = w ? Wa2 : Wa1;
    __shared__ float ae[WD_];
    int aidx = arg[b];
    for (int d = threadIdx.x; d < WD_; d += blockDim.x)
        ae[d] = wemb[aidx*WD_ + d];
    __syncthreads();
    int warp = threadIdx.x >> 5, lane = threadIdx.x & 31;
    for (int e = warp; e < ATTN_; e += 8) {
        const float* row = Wa + e*ATTN_ + IN_DIM_;
        float s = 0.f;
        for (int d = lane; d < WD_; d += 32) s += ae[d] * row[d];
        #pragma unroll
        for (int off = 16; off > 0; off >>= 1)
            s += __shfl_xor_sync(0xffffffffu, s, off);
        if (lane == 0) g_c[w][b*ATTN_ + e] = s;
    }
}

// ---------------- unified GEMM: 4-stage cp.async pipeline ----------------
__global__ __launch_bounds__(256, 2) void k_gemm(const float* __restrict__ wr1,
                                                 const float* __restrict__ wr2) {
    extern __shared__ float smem[];
    __shared__ float cs[128], wrs[128];
    uint32_t sb = (uint32_t)__cvta_generic_to_shared(smem);

    int bid = blockIdx.x;
    int tid = threadIdx.x;
    int lane = tid & 31, warp = tid >> 5;
    int warpM = warp & 1, warpN = warp >> 1;
    int g = lane >> 2, t = lane & 3;
    int lr = tid >> 1;            // loader row 0..127
    int jb = (tid & 1) * 2;       // loader 16B-group base (groups 0..3 per row)

    float acc[4][4][4];
    #pragma unroll
    for (int mi = 0; mi < 4; ++mi)
        #pragma unroll
        for (int ni = 0; ni < 4; ++ni)
            #pragma unroll
            for (int c = 0; c < 4; ++c) acc[mi][ni][c] = 0.f;

    // per-stage base addresses
    uint32_t abuf[NSTG], bbuf[NSTG];
    #pragma unroll
    for (int s = 0; s < NSTG; ++s) {
        abuf[s] = sb + (2*s    )*TILE_W*4;
        bbuf[s] = sb + (2*s + 1)*TILE_W*4;
    }

    bool isconv = bid < 1024;
    int b, n0, NT;
    const float* Asrc;
    const float* Bsrc;
    int w = 0, chunk = 0;
    if (isconv) {
        n0 = (bid & 3) << 7;
        b  = bid >> 2;
        NT = KC_/KT_;               // 76
        Bsrc = g_WtT;
        Asrc = g_inpm;
    } else {
        int id = bid - 1024;
        w = id & 1;
        chunk = (id >> 1) % 6;
        b = id / 12;
        n0 = chunk * 128;
        NT = KA_/KT_;               // 26
        Bsrc = &g_WaTp[w*NPADA*KA_];
        Asrc = g_inpm;
        const float* wr = w ? wr2 : wr1;
        const float* cb = &g_c[w][b*ATTN_];
        if (tid < 128) {
            int n = n0 + tid;
            cs[tid]  = (n < ATTN_) ? cb[n] : 0.f;
            wrs[tid] = (n < ATTN_) ? wr[n] : 0.f;
        }
    }

    // tile loader: tile kt into stage s
    auto load_tile = [&](int kt, int s) {
        int k0 = kt * KT_;
        #pragma unroll
        for (int j = 0; j < 2; ++j) {
            int grp = jb + j;             // 0..3
            int k = k0 + grp * 4;
            const float* srcA;
            if (isconv) {
                int h, i;
                if (k < 1200) { h = k / 400; i = k - h*400; }
                else          { h = 0;       i = k - 800; }
                srcA = &Asrc[(b*ROWSP + lr + h)*IN_PAD + i];
            } else {
                srcA = &Asrc[(b*ROWSP + lr + 1)*IN_PAD + k];
            }
            cpa16(abuf[s] + (lr*LDA + grp*4)*4, srcA);
            cpa16(bbuf[s] + (lr*LDA + grp*4)*4,
                  isconv ? &Bsrc[(n0 + lr)*KC_ + k] : &Bsrc[(n0 + lr)*KA_ + k]);
        }
        CP_COMMIT();
    };

    // prologue: stages 0,1,2
    load_tile(0, 0);
    load_tile(1, 1);
    load_tile(2, 2);

    for (int kt = 0; kt < NT; ++kt) {
        CP_WAIT(2);
        __syncthreads();
        // issue next load into the stage whose compute the barrier just retired
        if (kt + 3 < NT) load_tile(kt + 3, (kt + 3) & 3);
        else             CP_COMMIT();      // empty group keeps wait arithmetic exact
        int s = kt & 3;
        #pragma unroll
        for (int ks = 0; ks < 2; ++ks) {
            int kb = ks * 8;
            uint32_t af[4][4], bf[4][2];
            #pragma unroll
            for (int mi = 0; mi < 4; ++mi) {
                int row = warpM*64 + mi*16 + (lane & 7) + ((lane >> 3) & 1)*8;
                ldsm4(af[mi], abuf[s] + (row*LDA + kb + ((lane >> 4) << 2))*4);
            }
            #pragma unroll
            for (int ni = 0; ni < 4; ++ni) {
                int row = warpN*32 + ni*8 + (lane & 7);
                ldsm2(bf[ni], bbuf[s] + (row*LDA + kb + (((lane >> 3) & 1) << 2))*4);
            }
            #pragma unroll
            for (int mi = 0; mi < 4; ++mi)
                #pragma unroll
                for (int ni = 0; ni < 4; ++ni)
                    MMA_TF32(acc[mi][ni], af[mi], bf[ni]);
        }
    }
    __syncthreads();    // protect smem reuse in epilogues

    if (isconv) {
        // fused time-max epilogue
        float cm[4][2];
        #pragma unroll
        for (int ni = 0; ni < 4; ++ni) { cm[ni][0] = -1e30f; cm[ni][1] = -1e30f; }
        #pragma unroll
        for (int mi = 0; mi < 4; ++mi)
            #pragma unroll
            for (int ni = 0; ni < 4; ++ni) {
                cm[ni][0] = fmaxf(cm[ni][0], fmaxf(acc[mi][ni][0], acc[mi][ni][2]));
                cm[ni][1] = fmaxf(cm[ni][1], fmaxf(acc[mi][ni][1], acc[mi][ni][3]));
            }
        #pragma unroll
        for (int off = 4; off < 32; off <<= 1)
            #pragma unroll
            for (int ni = 0; ni < 4; ++ni) {
                cm[ni][0] = fmaxf(cm[ni][0], __shfl_xor_sync(0xffffffffu, cm[ni][0], off));
                cm[ni][1] = fmaxf(cm[ni][1], __shfl_xor_sync(0xffffffffu, cm[ni][1], off));
            }
        float* smax = smem;
        if (g == 0) {
            #pragma unroll
            for (int ni = 0; ni < 4; ++ni) {
                int col = warpN*32 + ni*8 + 2*t;
                smax[warpM*128 + col]     = cm[ni][0];
                smax[warpM*128 + col + 1] = cm[ni][1];
            }
        }
        __syncthreads();
        if (tid < 128)
            g_cnnmax[b*NF_ + n0 + tid] = fmaxf(smax[tid], smax[128 + tid]);
    } else {
        // fused tanh + wr-dot epilogue
        float rowacc[4][2];
        #pragma unroll
        for (int mi = 0; mi < 4; ++mi) {
            #pragma unroll
            for (int rr = 0; rr < 2; ++rr) {
                float rp = 0.f;
                #pragma unroll
                for (int ni = 0; ni < 4; ++ni)
                    #pragma unroll
                    for (int c = 0; c < 2; ++c) {
                        int col = warpN*32 + ni*8 + 2*t + c;
                        rp += wrs[col] * tanhf(acc[mi][ni][rr*2 + c] + cs[col]);
                    }
                rowacc[mi][rr] = rp;
            }
        }
        #pragma unroll
        for (int off = 1; off < 4; off <<= 1)
            #pragma unroll
            for (int mi = 0; mi < 4; ++mi)
                #pragma unroll
                for (int rr = 0; rr < 2; ++rr)
                    rowacc[mi][rr] += __shfl_xor_sync(0xffffffffu, rowacc[mi][rr], off);
        float* red = smem;
        if (t == 0) {
            #pragma unroll
            for (int mi = 0; mi < 4; ++mi)
                #pragma unroll
                for (int rr = 0; rr < 2; ++rr) {
                    int row = warpM*64 + mi*16 + g + rr*8;
                    red[warpN*128 + row] = rowacc[mi][rr];
                }
        }
        __syncthreads();
        if (tid < 128) {
            float s = red[tid] + red[128 + tid] + red[256 + tid] + red[384 + tid];
            g_spart[(w*6 + chunk)*M_ + b*T_ + tid] = s;
        }
    }
}

// ---------------- fused softmax + wsum + final dense + softmax ----------------
__global__ __launch_bounds__(512) void k_post(const float* __restrict__ mask,
                                              const float* __restrict__ conv_b,
                                              const float* __restrict__ dw,
                                              const float* __restrict__ db,
                                              float* __restrict__ out) {
    int b = blockIdx.x;
    int tid = threadIdx.x;
    __shared__ float aw[2][128];
    __shared__ float sh[2][128];
    __shared__ float feat[FEAT_];
    __shared__ float lg[NCLS_];
    int w = (tid >> 7) & 1, t = tid & 127;

    float s = 0.f, e = 0.f;
    if (tid < 256) {
        #pragma unroll
        for (int c = 0; c < 6; ++c) s += g_spart[(w*6 + c)*M_ + b*T_ + t];
        if (mask[b*T_ + t] == 0.f) s = -1e30f;
        sh[w][t] = s;
    }
    __syncthreads();
    for (int o = 64; o > 0; o >>= 1) {
        if (tid < 256 && t < o) sh[w][t] = fmaxf(sh[w][t], sh[w][t + o]);
        __syncthreads();
    }
    float mx = (tid < 256) ? sh[w][0] : 0.f;
    __syncthreads();
    if (tid < 256) { e = expf(s - mx); sh[w][t] = e; }
    __syncthreads();
    for (int o = 64; o > 0; o >>= 1) {
        if (tid < 256 && t < o) sh[w][t] += sh[w][t + o];
        __syncthreads();
    }
    if (tid < 256) aw[w][t] = e / sh[w][0];
    __syncthreads();

    for (int idx = tid; idx < 2*IN_DIM_; idx += 512) {
        int w2 = idx / IN_DIM_, d = idx % IN_DIM_;
        float s2 = 0.f;
        #pragma unroll 4
        for (int t2 = 0; t2 < T_; ++t2)
            s2 += aw[w2][t2] * g_inpm[(b*ROWSP + t2 + 1)*IN_PAD + d];
        feat[NF_ + idx] = s2;
    }
    feat[tid] = tanhf(g_cnnmax[b*NF_ + tid] + conv_b[tid]);
    __syncthreads();

    int warp = tid >> 5, lane = tid & 31;
    for (int c = warp; c < NCLS_; c += 16) {
        float s3 = 0.f;
        for (int i = lane; i < FEAT_; i += 32) s3 += feat[i] * dw[c*FEAT_ + i];
        #pragma unroll
        for (int off = 16; off > 0; off >>= 1)
            s3 += __shfl_xor_sync(0xffffffffu, s3, off);
        if (lane == 0) lg[c] = s3 + db[c];
    }
    __syncthreads();
    if (tid == 0) {
        float mx2 = lg[0];
        #pragma unroll
        for (int c = 1; c < NCLS_; ++c) mx2 = fmaxf(mx2, lg[c]);
        float sm = 0.f, ee[NCLS_];
        #pragma unroll
        for (int c = 0; c < NCLS_; ++c) { ee[c] = expf(lg[c] - mx2); sm += ee[c]; }
        #pragma unroll
        for (int c = 0; c < NCLS_; ++c) out[b*NCLS_ + c] = ee[c] / sm;
    }
}

// ---------------- launch ----------------
extern "C" void kernel_launch(void* const* d_in, const int* in_sizes, int n_in,
                              void* d_out, int out_size) {
    const int*   words  = (const int*)d_in[0];
    const float* mask   = (const float*)d_in[1];
    const int*   d1i    = (const int*)d_in[2];
    const int*   d2i    = (const int*)d_in[3];
    const int*   arg1   = (const int*)d_in[7];
    const int*   arg2   = (const int*)d_in[8];
    const float* wemb   = (const float*)d_in[9];
    const float* d1e    = (const float*)d_in[10];
    const float* d2e    = (const float*)d_in[11];
    const float* Wa1    = (const float*)d_in[12];
    const float* wr1    = (const float*)d_in[13];
    const float* Wa2    = (const float*)d_in[14];
    const float* wr2    = (const float*)d_in[15];
    const float* conv_w = (const float*)d_in[16];
    const float* conv_b = (const float*)d_in[17];
    const float* dw     = (const float*)d_in[18];
    const float* db     = (const float*)d_in[19];
    float* out = (float*)d_out;

    cudaFuncSetAttribute(k_gemm, cudaFuncAttributeMaxDynamicSharedMemorySize, SMEM_BYTES);

    const int NPREP = NF_*KC_ + 2*NPADA*KA_;
    k_prep<<<(NPREP + 255)/256, 256>>>(conv_w, Wa1, Wa2);
    k_gather<<<(B_*ROWSP*IN_PAD + 255)/256, 256>>>(words, d1i, d2i, wemb, d1e, d2e, mask);
    k_argc<<<dim3(B_, 2), 256>>>(arg1, arg2, wemb, Wa1, Wa2);
    k_gemm<<<4096, 256, SMEM_BYTES>>>(wr1, wr2);
    k_post<<<B_, 512>>>(mask, conv_b, dw, db, out);
}